// round 12
// baseline (speedup 1.0000x reference)
#include <cuda_runtime.h>
#include <cstdint>

// Problem constants
#define DDIM 4096
#define NEXP 64
#define NTOK 16384          // B*S
#define BM   128
#define KC   32             // K per stage
#define NSTAGE (DDIM / KC)  // 128
#define NCTA (NTOK / BM)    // 128
#define S36  36             // smem row stride (36 mod 32 = 4 -> conflict-free frags)

// Output layout (tuple flattened to float32 in reference order)
#define IDX_OFF   0
#define SC_OFF    32768
#define PB_OFF    65536
#define Z_OFF     1114112
#define IMP_OFF   1114113
#define LOAD_OFF  1114177

// Dynamic smem (float offsets): xh[2]@0/4608, xl[2]@9216/13824,
// wh[2]@18432/20736, wl[2]@23040/25344. Total 27648 floats = 108KB.
// After mainloop: ls[128][65] @0, st[129] @8320 (reuse).
#define XH(b) ((b) * 4608)
#define XL(b) (9216 + (b) * 4608)
#define WH(b) (18432 + (b) * 2304)
#define WL(b) (23040 + (b) * 2304)
#define DSM_BYTES (27648 * 4)

// Per-CTA partial stats: [0..63] importance, [64..127] counts, [128] z^2
__device__ float g_part[NCTA][129];
__device__ unsigned int g_ctr = 0;   // self-resetting via atomicInc wrap

// ---------- helpers ----------
__device__ __forceinline__ void tf32pair(float v, uint32_t& h, uint32_t& l) {
    asm("cvt.rna.tf32.f32 %0, %1;" : "=r"(h) : "f"(v));
    float r = v - __uint_as_float(h);
    asm("cvt.rna.tf32.f32 %0, %1;" : "=r"(l) : "f"(r));
}
__device__ __forceinline__ void mma8(float* d,
                                     uint32_t a0, uint32_t a1, uint32_t a2, uint32_t a3,
                                     uint32_t b0, uint32_t b1) {
    asm volatile(
        "mma.sync.aligned.m16n8k8.row.col.f32.tf32.tf32.f32 "
        "{%0,%1,%2,%3},{%4,%5,%6,%7},{%8,%9},{%0,%1,%2,%3};"
        : "+f"(d[0]), "+f"(d[1]), "+f"(d[2]), "+f"(d[3])
        : "r"(a0), "r"(a1), "r"(a2), "r"(a3), "r"(b0), "r"(b1));
}
__device__ __forceinline__ void ldsm4(uint32_t& r0, uint32_t& r1,
                                      uint32_t& r2, uint32_t& r3, uint32_t addr) {
    asm volatile("ldmatrix.sync.aligned.m8n8.x4.shared.b16 {%0,%1,%2,%3}, [%4];"
                 : "=r"(r0), "=r"(r1), "=r"(r2), "=r"(r3) : "r"(addr));
}

// ---------- single fused kernel ----------
// grid = 128 CTAs, block = 512 threads (16 warps, 4/SMSP).
// K-split: tile = warp>>1 (4 rowblocks x 2 expert halves, 32x32 each),
// ks = warp&1 -> MMA only on stages with s&1 == ks (buffer ks). Each warp
// accumulates half of K; partials summed in the epilogue.
extern "C" __global__ void __launch_bounds__(512, 1)
router_kernel(const float* __restrict__ x, const float* __restrict__ W,
              float* __restrict__ out) {
    extern __shared__ __align__(16) float dsm[];

    const int tid  = threadIdx.x;
    const int warp = tid >> 5;
    const int lane = tid & 31;
    const int g = lane >> 2;      // group row
    const int t = lane & 3;       // thread-in-group
    const int rowbase = blockIdx.x * BM;
    const float* xg0 = x + (size_t)rowbase * DDIM;

    const int tile  = warp >> 1;          // 0..7
    const int ks    = warp & 1;           // K half (stage parity)
    const int wrow  = (tile >> 1) * 32;   // 4 row blocks of 32
    const int cbase = (tile & 1) * 32;    // 2 expert halves

    uint32_t dsm_a;
    asm("{ .reg .u64 t0; cvta.to.shared.u64 t0, %1; cvt.u32.u64 %0, t0; }"
        : "=r"(dsm_a) : "l"(dsm));

    // ldmatrix lane address (element offset within a tile buffer)
    const int arow = wrow + (lane & 7) + ((lane >> 3) & 1) * 8;
    const int aoff = arow * S36 + ((lane >> 4) & 1) * 4;

    // ---- register-prefetch double-buffered loader ----
    // x: 1024 quads/stage -> 2 per thread; w: 512 quads -> 1 per thread.
    float4 xr[2], wr;
    #pragma unroll
    for (int i = 0; i < 2; i++) {
        int c = tid + 512 * i, r = c >> 3, q = c & 7;
        xr[i] = *(const float4*)(xg0 + (size_t)r * DDIM + (q << 2));
    }
    {
        int r = tid >> 3, q = tid & 7;
        wr = *(const float4*)(W + (size_t)r * DDIM + (q << 2));
    }

    float acc[2][4][4];   // [row block][n tile][frag]
    #pragma unroll
    for (int rb = 0; rb < 2; rb++)
        #pragma unroll
        for (int nt = 0; nt < 4; nt++)
            #pragma unroll
            for (int e = 0; e < 4; e++) acc[rb][nt][e] = 0.0f;

    #pragma unroll 1
    for (int s = 0; s < NSTAGE; s++) {
        const int b = s & 1;

        // prefetch next stage
        float4 xn[2], wn;
        if (s + 1 < NSTAGE) {
            const float* xg = xg0 + (s + 1) * KC;
            const float* wg = W + (s + 1) * KC;
            #pragma unroll
            for (int i = 0; i < 2; i++) {
                int c = tid + 512 * i, r = c >> 3, q = c & 7;
                xn[i] = *(const float4*)(xg + (size_t)r * DDIM + (q << 2));
            }
            {
                int r = tid >> 3, q = tid & 7;
                wn = *(const float4*)(wg + (size_t)r * DDIM + (q << 2));
            }
        }

        // convert current stage fp32 -> (tf32 hi, tf32 lo), store to smem
        #pragma unroll
        for (int i = 0; i < 2; i++) {
            int c = tid + 512 * i, r = c >> 3, q = c & 7;
            uint4 h, l;
            tf32pair(xr[i].x, h.x, l.x);
            tf32pair(xr[i].y, h.y, l.y);
            tf32pair(xr[i].z, h.z, l.z);
            tf32pair(xr[i].w, h.w, l.w);
            int off = r * S36 + (q << 2);
            *(uint4*)(dsm + XH(b) + off) = h;
            *(uint4*)(dsm + XL(b) + off) = l;
        }
        {
            int r = tid >> 3, q = tid & 7;
            uint4 h, l;
            tf32pair(wr.x, h.x, l.x);
            tf32pair(wr.y, h.y, l.y);
            tf32pair(wr.z, h.z, l.z);
            tf32pair(wr.w, h.w, l.w);
            int off = r * S36 + (q << 2);
            *(uint4*)(dsm + WH(b) + off) = h;
            *(uint4*)(dsm + WL(b) + off) = l;
        }
        __syncthreads();

        // ---- MMA phase (only warps whose parity matches this stage) ----
        if (b == ks) {
            const uint32_t ah_base = dsm_a + (uint32_t)(XH(b) + aoff) * 4;
            const uint32_t al_base = dsm_a + (uint32_t)(XL(b) + aoff) * 4;
            const uint32_t* wh = (const uint32_t*)(dsm + WH(b)) + (cbase + g) * S36 + t;
            const uint32_t* wl = (const uint32_t*)(dsm + WL(b)) + (cbase + g) * S36 + t;

            #pragma unroll
            for (int kq = 0; kq < 4; kq++) {
                const int k0 = kq * 8;
                uint32_t ah[2][4], al[2][4];
                #pragma unroll
                for (int rb = 0; rb < 2; rb++) {
                    ldsm4(ah[rb][0], ah[rb][1], ah[rb][2], ah[rb][3],
                          ah_base + (uint32_t)(rb * 16 * S36 + k0) * 4);
                    ldsm4(al[rb][0], al[rb][1], al[rb][2], al[rb][3],
                          al_base + (uint32_t)(rb * 16 * S36 + k0) * 4);
                }
                #pragma unroll
                for (int nt = 0; nt < 4; nt++) {
                    const uint32_t* wph = wh + nt * 8 * S36;
                    const uint32_t* wpl = wl + nt * 8 * S36;
                    uint32_t bh0 = wph[k0], bh1 = wph[k0 + 4];
                    uint32_t bl0 = wpl[k0], bl1 = wpl[k0 + 4];
                    #pragma unroll
                    for (int rb = 0; rb < 2; rb++) {
                        mma8(acc[rb][nt], al[rb][0], al[rb][1], al[rb][2], al[rb][3],
                             bh0, bh1);                                       // lh
                        mma8(acc[rb][nt], ah[rb][0], ah[rb][1], ah[rb][2], ah[rb][3],
                             bl0, bl1);                                       // hl
                        mma8(acc[rb][nt], ah[rb][0], ah[rb][1], ah[rb][2], ah[rb][3],
                             bh0, bh1);                                       // hh
                    }
                }
            }
        }

        #pragma unroll
        for (int i = 0; i < 2; i++) xr[i] = xn[i];
        wr = wn;
    }
    __syncthreads();   // all MMAs done before smem reuse

    // ---- epilogue: two-phase logits write (K halves summed) ----
    float* ls = dsm;
    float* st = dsm + 8320;
    if (ks == 0) {
        #pragma unroll
        for (int rb = 0; rb < 2; rb++)
            #pragma unroll
            for (int nt = 0; nt < 4; nt++) {
                const int c0 = cbase + nt * 8 + 2 * t;
                const int r0 = wrow + rb * 16 + g;
                ls[r0 * 65 + c0]           = acc[rb][nt][0];
                ls[r0 * 65 + c0 + 1]       = acc[rb][nt][1];
                ls[(r0 + 8) * 65 + c0]     = acc[rb][nt][2];
                ls[(r0 + 8) * 65 + c0 + 1] = acc[rb][nt][3];
            }
    }
    if (tid < 129) st[tid] = 0.0f;
    __syncthreads();
    if (ks == 1) {
        #pragma unroll
        for (int rb = 0; rb < 2; rb++)
            #pragma unroll
            for (int nt = 0; nt < 4; nt++) {
                const int c0 = cbase + nt * 8 + 2 * t;
                const int r0 = wrow + rb * 16 + g;
                ls[r0 * 65 + c0]           += acc[rb][nt][0];
                ls[r0 * 65 + c0 + 1]       += acc[rb][nt][1];
                ls[(r0 + 8) * 65 + c0]     += acc[rb][nt][2];
                ls[(r0 + 8) * 65 + c0 + 1] += acc[rb][nt][3];
            }
    }
    __syncthreads();

    // ---- router: 16 warps, 8 rows per warp ----
    const float NEG_INF = __int_as_float(0xff800000u);
    float imp0 = 0.f, imp1 = 0.f, cnt0 = 0.f, cnt1 = 0.f, z2 = 0.f;
    float* probs_out = out + PB_OFF;

    #pragma unroll 2
    for (int it = 0; it < 8; it++) {
        const int rl = warp * 8 + it;
        const int row = rowbase + rl;
        const float va = ls[rl * 65 + lane];
        const float vb = ls[rl * 65 + lane + 32];

        float bv; int bi;
        if (va >= vb) { bv = va; bi = lane; } else { bv = vb; bi = lane + 32; }
        #pragma unroll
        for (int off = 16; off; off >>= 1) {
            float ov = __shfl_xor_sync(0xffffffffu, bv, off);
            int   oi = __shfl_xor_sync(0xffffffffu, bi, off);
            if (ov > bv || (ov == bv && oi < bi)) { bv = ov; bi = oi; }
        }
        float va2 = (lane == bi)      ? NEG_INF : va;
        float vb2 = (lane + 32 == bi) ? NEG_INF : vb;
        float sv; int si;
        if (va2 >= vb2) { sv = va2; si = lane; } else { sv = vb2; si = lane + 32; }
        #pragma unroll
        for (int off = 16; off; off >>= 1) {
            float ov = __shfl_xor_sync(0xffffffffu, sv, off);
            int   oi = __shfl_xor_sync(0xffffffffu, si, off);
            if (ov > sv || (ov == sv && oi < si)) { sv = ov; si = oi; }
        }

        const float ea = __expf(va - bv);
        const float eb = __expf(vb - bv);
        float ssum = ea + eb;
        #pragma unroll
        for (int off = 16; off; off >>= 1)
            ssum += __shfl_xor_sync(0xffffffffu, ssum, off);
        const float inv = 1.0f / ssum;
        const float pa = ea * inv, pb = eb * inv;

        probs_out[(size_t)row * 64 + lane]      = pa;
        probs_out[(size_t)row * 64 + lane + 32] = pb;

        imp0 += pa; imp1 += pb;
        cnt0 += (bi == lane      ? 1.f : 0.f) + (si == lane      ? 1.f : 0.f);
        cnt1 += (bi == lane + 32 ? 1.f : 0.f) + (si == lane + 32 ? 1.f : 0.f);

        if (lane == 0) {
            const float z = bv + __logf(ssum);
            z2 += z * z;
            out[IDX_OFF + row * 2]     = (float)bi;
            out[IDX_OFF + row * 2 + 1] = (float)si;
            const float e2 = __expf(sv - bv);
            const float dn = 1.0f / (1.0f + e2);
            out[SC_OFF + row * 2]     = dn;
            out[SC_OFF + row * 2 + 1] = e2 * dn;
        }
    }

    // ---- CTA-level stats reduce in smem, then one row of g_part ----
    atomicAdd(&st[lane],      imp0);
    atomicAdd(&st[lane + 32], imp1);
    atomicAdd(&st[64 + lane], cnt0);
    atomicAdd(&st[96 + lane], cnt1);
    if (lane == 0) atomicAdd(&st[128], z2);
    __syncthreads();

    if (tid < 129) g_part[blockIdx.x][tid] = st[tid];

    // ---- last-CTA finalize (self-resetting counter) ----
    __shared__ unsigned int s_last;
    __threadfence();
    __syncthreads();
    if (tid == 0) {
        unsigned int old = atomicInc(&g_ctr, NCTA - 1);
        s_last = (old == NCTA - 1) ? 1u : 0u;
    }
    __syncthreads();
    if (s_last && tid < 129) {
        __threadfence();
        float ssum = 0.f;
        #pragma unroll 1
        for (int c = 0; c < NCTA; c++) ssum += g_part[c][tid];
        if (tid < 64)       out[IMP_OFF + tid]         = ssum * (1.0f / 16384.0f);
        else if (tid < 128) out[LOAD_OFF + (tid - 64)] = ssum * (1.0f / 32768.0f);
        else                out[Z_OFF]                 = ssum * (1.0f / 16384.0f);
    }
}

extern "C" void kernel_launch(void* const* d_in, const int* in_sizes, int n_in,
                              void* d_out, int out_size) {
    const float* x = (const float*)d_in[0];   // [4,4096,4096] f32
    const float* W = (const float*)d_in[1];   // [64,4096] f32
    float* out = (float*)d_out;
    (void)in_sizes; (void)n_in; (void)out_size;
    cudaFuncSetAttribute(router_kernel, cudaFuncAttributeMaxDynamicSharedMemorySize,
                         DSM_BYTES);
    router_kernel<<<NCTA, 512, DSM_BYTES>>>(x, W, out);
}